// round 10
// baseline (speedup 1.0000x reference)
#include <cuda_runtime.h>
#include <cstdint>
#include <math.h>

#define T_STEPS 1000
#define BATCH   4096
#define T_EXACT 224
#define CHUNK   8
#define NCHUNK_EXACT 28                    // 224 / 8
#define NCHUNKS (T_STEPS / CHUNK)          // 125

#define MEANS_ELEMS ((size_t)T_STEPS * BATCH * 8)
#define CONS_THREADS 224                   // warps 1..7 consume; warp 0 produces
#define NB_MEAN  37                        // ceil(4096 / (224/2))
#define NB_TOTAL (NB_MEAN + T_STEPS)       // 1037
#define THREADS  256
#define FULLMASK 0xffffffffu

// cofactor (r,c) of a 4x4, element index l = r*4+c
template <typename T>
__device__ __forceinline__ float cof4t(const T* S, int l) {
    int r = l >> 2, c = l & 3;
    int ra[3], ca[3];
    int n = 0;
    #pragma unroll
    for (int x = 0; x < 4; x++) if (x != r) ra[n++] = x;
    n = 0;
    #pragma unroll
    for (int x = 0; x < 4; x++) if (x != c) ca[n++] = x;
    double m00 = S[ra[0]*4+ca[0]], m01 = S[ra[0]*4+ca[1]], m02 = S[ra[0]*4+ca[2]];
    double m10 = S[ra[1]*4+ca[0]], m11 = S[ra[1]*4+ca[1]], m12 = S[ra[1]*4+ca[2]];
    double m20 = S[ra[2]*4+ca[0]], m21 = S[ra[2]*4+ca[1]], m22 = S[ra[2]*4+ca[2]];
    double d = m00*(m11*m22 - m12*m21) - m01*(m10*m22 - m12*m20) + m02*(m10*m21 - m11*m20);
    return (float)(((r + c) & 1) ? -d : d);
}

// warp-collective fp32 8x8 inverse, Gauss-Jordan + partial pivoting (proven R6-R9)
__device__ void inv8x8_f(const float* A, float* Ainv, int l) {
    float rA[8], rI[8];
    #pragma unroll
    for (int j = 0; j < 8; j++) {
        rA[j] = (l < 8) ? A[l*8 + j] : 0.f;
        rI[j] = (l == j) ? 1.f : 0.f;
    }
    #pragma unroll 1
    for (int k = 0; k < 8; k++) {
        float cand = (l >= k && l < 8) ? fabsf(rA[k]) : -1.f;
        int idx = (l < 8) ? l : 0;
        #pragma unroll
        for (int d = 1; d < 8; d <<= 1) {
            float oc = __shfl_xor_sync(FULLMASK, cand, d);
            int   oi = __shfl_xor_sync(FULLMASK, idx,  d);
            if (oc > cand || (oc == cand && oi < idx)) { cand = oc; idx = oi; }
        }
        const int piv = __shfl_sync(FULLMASK, idx, 0);
        const int src = (l == k) ? piv : ((l == piv) ? k : l);
        #pragma unroll
        for (int j = 0; j < 8; j++) {
            rA[j] = __shfl_sync(FULLMASK, rA[j], src);
            rI[j] = __shfl_sync(FULLMASK, rI[j], src);
        }
        float pA[8], pI[8];
        #pragma unroll
        for (int j = 0; j < 8; j++) {
            pA[j] = __shfl_sync(FULLMASK, rA[j], k);
            pI[j] = __shfl_sync(FULLMASK, rI[j], k);
        }
        const float inv = 1.f / pA[k];
        if (l == k) {
            #pragma unroll
            for (int j = 0; j < 8; j++) { rA[j] = pA[j]*inv; rI[j] = pI[j]*inv; }
        } else {
            const float f = rA[k] * inv;
            #pragma unroll
            for (int j = 0; j < 8; j++) { rA[j] -= f*pA[j]; rI[j] -= f*pI[j]; }
        }
    }
    if (l < 8) {
        #pragma unroll
        for (int j = 0; j < 8; j++) Ainv[l*8 + j] = rI[j];
    }
}

// One SDA doubling of the triple (W,V,U) in place (proven R6-R9). scr: 256.
__device__ void sda_double(float* sW, float* sV, float* sU, float* scr, int l)
{
    float* phA = scr; float* phT = scr + 64; float* phB = scr + 128; float* phD = scr + 192;
    const int i0 = l >> 3, j = l & 7;
    {
        float s0 = 0.f, s1 = 0.f;
        #pragma unroll
        for (int k = 0; k < 8; k++) {
            const float ukj = sU[k*8 + j];
            s0 += sW[i0*8 + k]     * ukj;
            s1 += sW[(i0+4)*8 + k] * ukj;
        }
        phA[i0*8 + j]     = s0 + (i0 == j     ? 1.f : 0.f);
        phA[(i0+4)*8 + j] = s1 + (i0 + 4 == j ? 1.f : 0.f);
    }
    __syncwarp();
    inv8x8_f(phA, phT, l);
    __syncwarp();
    {
        float b0 = 0.f, b1 = 0.f, d0 = 0.f, d1 = 0.f;
        #pragma unroll
        for (int k = 0; k < 8; k++) {
            const float tkj = phT[k*8 + j];
            b0 += sV[i0*8 + k]     * tkj;
            b1 += sV[(i0+4)*8 + k] * tkj;
            d0 += sU[i0*8 + k]     * tkj;
            d1 += sU[(i0+4)*8 + k] * tkj;
        }
        phB[i0*8 + j] = b0;  phB[(i0+4)*8 + j] = b1;
        phD[i0*8 + j] = d0;  phD[(i0+4)*8 + j] = d1;
    }
    __syncwarp();
    {
        float c0 = 0.f, c1 = 0.f, e0 = 0.f, e1 = 0.f;
        #pragma unroll
        for (int k = 0; k < 8; k++) {
            const float wkj = sW[k*8 + j], vkj = sV[k*8 + j];
            c0 += phB[i0*8 + k]     * wkj;
            c1 += phB[(i0+4)*8 + k] * wkj;
            e0 += phD[i0*8 + k]     * vkj;
            e1 += phD[(i0+4)*8 + k] * vkj;
        }
        __syncwarp();
        phA[i0*8 + j] = c0;  phA[(i0+4)*8 + j] = c1;
        phT[i0*8 + j] = e0;  phT[(i0+4)*8 + j] = e1;
    }
    __syncwarp();
    {
        float wn0 = sW[i0*8 + j], wn1 = sW[(i0+4)*8 + j];
        float un0 = sU[i0*8 + j], un1 = sU[(i0+4)*8 + j];
        float vn0 = 0.f, vn1 = 0.f;
        #pragma unroll
        for (int k = 0; k < 8; k++) {
            wn0 += phA[i0*8 + k]     * sV[j*8 + k];
            wn1 += phA[(i0+4)*8 + k] * sV[j*8 + k];
            un0 += sV[k*8 + i0]      * phT[k*8 + j];
            un1 += sV[k*8 + i0 + 4]  * phT[k*8 + j];
            vn0 += phB[i0*8 + k]     * sV[k*8 + j];
            vn1 += phB[(i0+4)*8 + k] * sV[k*8 + j];
        }
        __syncwarp();
        sW[i0*8 + j] = wn0;  sW[(i0+4)*8 + j] = wn1;
        sU[i0*8 + j] = un0;  sU[(i0+4)*8 + j] = un1;
        sV[i0*8 + j] = vn0;  sV[(i0+4)*8 + j] = vn1;
    }
    __syncwarp();
}

// Composition Phi_c = Phi_a ∘ Phi_b (proven R8/R9 in production). scr: 256.
__device__ void compose_triple(
    const float* Wa, const float* Va, const float* Ua,
    const float* Wb, const float* Vb, const float* Ub,
    float* Wc, float* Vc, float* Uc, float* scr, int l)
{
    const int i0 = l >> 3, j = l & 7;
    float* M1 = scr;
    float* T  = scr + 64;
    float* X  = scr + 128;
    float* N  = scr + 192;
    {
        float s0 = 0.f, s1 = 0.f;
        #pragma unroll
        for (int k = 0; k < 8; k++) {
            const float u = Ua[k*8 + j];
            s0 += Wb[i0*8 + k]     * u;
            s1 += Wb[(i0+4)*8 + k] * u;
        }
        M1[i0*8 + j]     = s0 + (i0 == j     ? 1.f : 0.f);
        M1[(i0+4)*8 + j] = s1 + (i0 + 4 == j ? 1.f : 0.f);
    }
    __syncwarp();
    inv8x8_f(M1, T, l);
    __syncwarp();
    {
        float x0 = 0.f, x1 = 0.f, n0 = 0.f, n1 = 0.f;
        #pragma unroll
        for (int k = 0; k < 8; k++) {
            const float t = T[k*8 + j];
            x0 += Va[i0*8 + k]     * t;
            x1 += Va[(i0+4)*8 + k] * t;
            n0 += Ua[i0*8 + k]     * t;
            n1 += Ua[(i0+4)*8 + k] * t;
        }
        X[i0*8 + j] = x0;  X[(i0+4)*8 + j] = x1;
        N[i0*8 + j] = n0;  N[(i0+4)*8 + j] = n1;
    }
    __syncwarp();
    {
        float v0 = 0.f, v1 = 0.f, w0 = 0.f, w1 = 0.f, q0 = 0.f, q1 = 0.f;
        #pragma unroll
        for (int k = 0; k < 8; k++) {
            const float vb = Vb[k*8 + j], wb = Wb[k*8 + j];
            v0 += X[i0*8 + k]     * vb;
            v1 += X[(i0+4)*8 + k] * vb;
            w0 += X[i0*8 + k]     * wb;
            w1 += X[(i0+4)*8 + k] * wb;
            q0 += N[i0*8 + k]     * vb;
            q1 += N[(i0+4)*8 + k] * vb;
        }
        __syncwarp();
        Vc[i0*8 + j] = v0;  Vc[(i0+4)*8 + j] = v1;
        M1[i0*8 + j] = w0;  M1[(i0+4)*8 + j] = w1;
        T [i0*8 + j] = q0;  T [(i0+4)*8 + j] = q1;
    }
    __syncwarp();
    {
        float wc0 = Wa[i0*8 + j], wc1 = Wa[(i0+4)*8 + j];
        float uc0 = Ub[i0*8 + j], uc1 = Ub[(i0+4)*8 + j];
        #pragma unroll
        for (int k = 0; k < 8; k++) {
            const float vajk = Va[j*8 + k], tkj = T[k*8 + j];
            wc0 += M1[i0*8 + k]     * vajk;
            wc1 += M1[(i0+4)*8 + k] * vajk;
            uc0 += Vb[k*8 + i0]     * tkj;
            uc1 += Vb[k*8 + i0 + 4] * tkj;
        }
        Wc[i0*8 + j] = wc0;  Wc[(i0+4)*8 + j] = wc1;
        Uc[i0*8 + j] = uc0;  Uc[(i0+4)*8 + j] = uc1;
    }
    __syncwarp();
}

// LFT apply: Pout = W + V P (I + U P)^-1 V^T (proven). scr: 256.
__device__ void apply_triple(const float* W, const float* V, const float* U,
                             const float* P, float* Pout, float* scr, int l)
{
    const int i0 = l >> 3, j = l & 7;
    float* M = scr;
    float* T = scr + 64;
    float* B = scr + 128;
    float* D = scr + 192;
    {
        float s0 = 0.f, s1 = 0.f;
        #pragma unroll
        for (int k = 0; k < 8; k++) {
            const float pkj = P[k*8 + j];
            s0 += U[i0*8 + k]     * pkj;
            s1 += U[(i0+4)*8 + k] * pkj;
        }
        M[i0*8 + j]     = s0 + (i0 == j     ? 1.f : 0.f);
        M[(i0+4)*8 + j] = s1 + (i0 + 4 == j ? 1.f : 0.f);
    }
    __syncwarp();
    inv8x8_f(M, T, l);
    __syncwarp();
    {
        float b0 = 0.f, b1 = 0.f;
        #pragma unroll
        for (int k = 0; k < 8; k++) {
            const float tkj = T[k*8 + j];
            b0 += P[i0*8 + k]     * tkj;
            b1 += P[(i0+4)*8 + k] * tkj;
        }
        B[i0*8 + j] = b0;  B[(i0+4)*8 + j] = b1;
    }
    __syncwarp();
    {
        float d0 = 0.f, d1 = 0.f;
        #pragma unroll
        for (int k = 0; k < 8; k++) {
            const float bkj = B[k*8 + j];
            d0 += V[i0*8 + k]     * bkj;
            d1 += V[(i0+4)*8 + k] * bkj;
        }
        D[i0*8 + j] = d0;  D[(i0+4)*8 + j] = d1;
    }
    __syncwarp();
    {
        float p0 = W[i0*8 + j], p1 = W[(i0+4)*8 + j];
        #pragma unroll
        for (int k = 0; k < 8; k++) {
            p0 += D[i0*8 + k]     * V[j*8 + k];
            p1 += D[(i0+4)*8 + k] * V[j*8 + k];
        }
        Pout[i0*8 + j] = p0;  Pout[(i0+4)*8 + j] = p1;
    }
    __syncwarp();
}

// One exact Riccati step (single warp, proven R6-R9 chain body).
// Writes row = [A_t (64) | K_t (32)]; advances Pw in place. c: scratch 288.
__device__ void riccati_step(const float* Fs, const float* Hs,
                             const float* Qs, const float* Rs,
                             float* Pw, float* row, float* c, int l, bool first)
{
    float* FPw = c;          float* HCw = c + 64;
    float* CHw = c + 96;     float* Sw  = c + 128;
    float* Cfw = c + 144;    float* Kw  = c + 160;
    float* Ww  = c + 192;    float* Mw  = c + 224;
    const int i0 = l >> 3, j = l & 7;
    const int qi = l >> 2, qj = l & 3;

    {
        float fp0 = 0.f, fp1 = 0.f, hc = 0.f, cht = 0.f;
        #pragma unroll
        for (int k = 0; k < 8; k++) {
            const float pkj = Pw[k*8 + j];
            fp0 += Fs[i0*8 + k]     * pkj;
            fp1 += Fs[(i0+4)*8 + k] * pkj;
            hc  += Hs[i0*8 + k]     * pkj;
            cht += Pw[qi*8 + k] * Hs[qj*8 + k];
        }
        FPw[l] = fp0;  FPw[32 + l] = fp1;
        HCw[l] = hc;   CHw[l] = cht;
    }
    __syncwarp();
    if (l < 16) {
        float sv = Rs[l];
        #pragma unroll
        for (int k = 0; k < 8; k++) sv += HCw[(l >> 2)*8 + k] * Hs[(l & 3)*8 + k];
        Sw[l] = sv;
    }
    __syncwarp();
    if (l < 16) Cfw[l] = cof4t<float>(Sw, l);
    __syncwarp();
    {
        const float det  = Sw[0]*Cfw[0] + Sw[1]*Cfw[1] + Sw[2]*Cfw[2] + Sw[3]*Cfw[3];
        const float rdet = 1.0f / det;
        float sv = 0.f;
        #pragma unroll
        for (int k = 0; k < 4; k++) sv += CHw[qi*4 + k] * Cfw[k*4 + qj];
        Kw[l] = sv * rdet;
    }
    __syncwarp();
    {
        float sm0 = 0.f, sm1 = 0.f, wv = 0.f;
        #pragma unroll
        for (int k = 0; k < 4; k++) {
            const float hskj = Hs[k*8 + j];
            sm0 += Kw[i0*4 + k]     * hskj;
            sm1 += Kw[(i0+4)*4 + k] * hskj;
        }
        #pragma unroll
        for (int k = 0; k < 8; k++) wv += Fs[qi*8 + k] * Kw[k*4 + qj];
        Mw[l]      = (i0 == j     ? 1.0f : 0.0f) - sm0;
        Mw[32 + l] = (i0 + 4 == j ? 1.0f : 0.0f) - sm1;
        Ww[l] = wv;
    }
    __syncwarp();
    {
        float a0, a1;
        if (first) { a0 = Mw[l];  a1 = Mw[32 + l]; }
        else {
            a0 = 0.f;  a1 = 0.f;
            #pragma unroll
            for (int k = 0; k < 8; k++) {
                const float fkj = Fs[k*8 + j];
                a0 += Mw[i0*8 + k]     * fkj;
                a1 += Mw[(i0+4)*8 + k] * fkj;
            }
        }
        row[l]      = a0;
        row[32 + l] = a1;
        row[64 + l] = Kw[l];

        const float w00 = Ww[i0*4+0],     w01 = Ww[i0*4+1],     w02 = Ww[i0*4+2],     w03 = Ww[i0*4+3];
        const float w10 = Ww[(i0+4)*4+0], w11 = Ww[(i0+4)*4+1], w12 = Ww[(i0+4)*4+2], w13 = Ww[(i0+4)*4+3];
        float p0 = Qs[l], p1 = Qs[32 + l];
        #pragma unroll
        for (int k = 0; k < 8; k++) {
            const float h0 = HCw[k], h1 = HCw[8+k], h2 = HCw[16+k], h3 = HCw[24+k];
            const float fjk = Fs[j*8 + k];
            const float fu0 = FPw[i0*8 + k]     - (w00*h0 + w01*h1 + w02*h2 + w03*h3);
            const float fu1 = FPw[(i0+4)*8 + k] - (w10*h0 + w11*h1 + w12*h2 + w13*h3);
            p0 += fu0 * fjk;
            p1 += fu1 * fjk;
        }
        Pw[l] = p0;  Pw[32 + l] = p1;
    }
    __syncwarp();
}

// ---------------------------------------------------------------------------
// SINGLE fused kernel — no setup launch, no inter-block dependencies.
//   blocks [0, NB_MEAN): producer-warp Riccati chain + R6-proven mean consumers
//   blocks [NB_MEAN, ..): per-block binary-expo Phi^t prologue + R6 bcast loop
// ---------------------------------------------------------------------------
__global__ void __launch_bounds__(THREADS, 4) fused_kernel(
    const float* __restrict__ obs,
    const float* __restrict__ F,
    const float* __restrict__ H,
    const float* __restrict__ Q,
    const float* __restrict__ R,
    const float* __restrict__ init_mean,
    const float* __restrict__ init_cov,
    float* __restrict__ out)
{
    __shared__ float Fs[64], Hs[32], Qs[64], Rs[16];
    __shared__ __align__(16) float sP[64], sP2[64];
    __shared__ float cur[192], accA[192], accB[192];
    __shared__ float scr[288];
    __shared__ __align__(16) float buf[2][CHUNK * 96];
    __shared__ __align__(16) float sU[64];

    const int tid = threadIdx.x;
    const int l   = tid & 31;

    if (blockIdx.x < NB_MEAN) {
        // ================= mean block: producer warp + consumers =================
        if (tid < 32) {
            // load inputs
            Fs[l] = F[l];  Fs[32 + l] = F[32 + l];
            Qs[l] = Q[l];  Qs[32 + l] = Q[32 + l];
            Hs[l] = H[l];
            if (l < 16) Rs[l] = R[l];
            sP[l] = init_cov[l];  sP[32 + l] = init_cov[32 + l];
            __syncwarp();
            // produce chunk 0
            #pragma unroll 1
            for (int s = 0; s < CHUNK; s++)
                riccati_step(Fs, Hs, Qs, Rs, sP, &buf[0][s*96], scr, l, (s == 0));
        }

        // consumer state (loaded concurrently with production)
        const int gtid = blockIdx.x * CONS_THREADS + (tid - 32);
        const int b    = gtid >> 1;
        const int half = gtid & 1;
        const bool act = (tid >= 32) && (b < BATCH);
        const int  bc  = (b < BATCH) ? b : (BATCH - 1);

        float st[8];
        if (tid >= 32) {
            #pragma unroll
            for (int i = 0; i < 8; i++) st[i] = init_mean[bc*8 + i];
        }
        __syncthreads();

        #pragma unroll 1
        for (int c = 0; c < NCHUNKS; c++) {
            if (tid < 32) {
                const int pc = c + 1;
                if (pc < NCHUNK_EXACT) {
                    #pragma unroll 1
                    for (int s = 0; s < CHUNK; s++)
                        riccati_step(Fs, Hs, Qs, Rs, sP,
                                     &buf[pc & 1][s*96], scr, l, false);
                }
            } else {
                const float* frozen = &buf[(NCHUNK_EXACT - 1) & 1][(CHUNK - 1)*96];
                #pragma unroll
                for (int u = 0; u < CHUNK; u++) {
                    const int t = c*CHUNK + u;
                    const float* Cs = (c < NCHUNK_EXACT) ? &buf[c & 1][u*96] : frozen;

                    const float4 zv = *reinterpret_cast<const float4*>(
                        &obs[((size_t)t*BATCH + bc) * 4]);

                    float y[4];
                    #pragma unroll
                    for (int r = 0; r < 4; r++) {
                        const int row = half*4 + r;
                        const float4 a0 = *reinterpret_cast<const float4*>(&Cs[row*8]);
                        const float4 a1 = *reinterpret_cast<const float4*>(&Cs[row*8 + 4]);
                        const float4 kk = *reinterpret_cast<const float4*>(&Cs[64 + row*4]);
                        y[r] = a0.x*st[0] + a0.y*st[1] + a0.z*st[2] + a0.w*st[3]
                             + a1.x*st[4] + a1.y*st[5] + a1.z*st[6] + a1.w*st[7]
                             + kk.x*zv.x + kk.y*zv.y + kk.z*zv.z + kk.w*zv.w;
                    }

                    if (act)
                        __stcs(reinterpret_cast<float4*>(
                                   &out[((size_t)t*BATCH + bc)*8 + half*4]),
                               make_float4(y[0], y[1], y[2], y[3]));

                    const float o0 = __shfl_xor_sync(FULLMASK, y[0], 1);
                    const float o1 = __shfl_xor_sync(FULLMASK, y[1], 1);
                    const float o2 = __shfl_xor_sync(FULLMASK, y[2], 1);
                    const float o3 = __shfl_xor_sync(FULLMASK, y[3], 1);
                    st[0] = half ? o0   : y[0];
                    st[1] = half ? o1   : y[1];
                    st[2] = half ? o2   : y[2];
                    st[3] = half ? o3   : y[3];
                    st[4] = half ? y[0] : o0;
                    st[5] = half ? y[1] : o1;
                    st[6] = half ? y[2] : o2;
                    st[7] = half ? y[3] : o3;
                }
            }
            __syncthreads();
        }
    } else {
        // ================= bcast block: self-sufficient Phi^t prologue =================
        const int t  = (int)blockIdx.x - NB_MEAN;            // 0..999
        const int tc = (t < T_EXACT) ? t : T_EXACT;

        if (tid < 32) {
            // load inputs
            Fs[l] = F[l];  Fs[32 + l] = F[32 + l];
            Qs[l] = Q[l];  Qs[32 + l] = Q[32 + l];
            Hs[l] = H[l];
            if (l < 16) Rs[l] = R[l];
            sP[l] = init_cov[l];  sP[32 + l] = init_cov[32 + l];
            __syncwarp();

            // E = H^T Rinv H ;  cur = (Q, F, E) = Phi^1
            if (l < 16) scr[l] = cof4t<float>(Rs, l);
            __syncwarp();
            {
                const int i0 = l >> 3, j = l & 7;
                const float det  = Rs[0]*scr[0] + Rs[1]*scr[1] + Rs[2]*scr[2] + Rs[3]*scr[3];
                const float rdet = 1.f / det;
                float e0 = 0.f, e1 = 0.f;
                #pragma unroll
                for (int a = 0; a < 4; a++) {
                    float t0 = 0.f;
                    #pragma unroll
                    for (int bb = 0; bb < 4; bb++) t0 += scr[bb*4 + a] * Hs[bb*8 + j];
                    t0 *= rdet;
                    e0 += Hs[a*8 + i0]     * t0;
                    e1 += Hs[a*8 + i0 + 4] * t0;
                }
                cur[128 + i0*8 + j] = e0;  cur[128 + (i0+4)*8 + j] = e1;   // U
                cur[l] = Qs[l];  cur[32 + l] = Qs[32 + l];                 // W
                cur[64 + l] = Fs[l];  cur[96 + l] = Fs[32 + l];            // V
            }
            __syncwarp();

            // binary exponentiation: acc = Phi^tc
            float* pA = accA;
            float* pB = accB;
            bool got = false;
            int rem = tc;
            #pragma unroll 1
            for (int bit = 0; bit < 8 && rem != 0; bit++) {
                if (rem & 1) {
                    if (!got) {
                        #pragma unroll
                        for (int e = 0; e < 6; e++) pA[e*32 + l] = cur[e*32 + l];
                        got = true;
                        __syncwarp();
                    } else {
                        compose_triple(cur, cur + 64, cur + 128,
                                       pA, pA + 64, pA + 128,
                                       pB, pB + 64, pB + 128, scr, l);
                        float* tmp = pA; pA = pB; pB = tmp;
                    }
                }
                rem >>= 1;
                if (rem != 0)
                    sda_double(cur, cur + 64, cur + 128, scr, l);
            }

            // P_t = Phi^tc(P0)
            const float* Pt = sP;
            if (got) {
                apply_triple(pA, pA + 64, pA + 128, sP, sP2, scr, l);
                Pt = sP2;
            }

            // derive U_t from P_t (proven update-stage math)
            {
                const int i0 = l >> 3, j = l & 7;
                const int qi = l >> 2, qj = l & 3;
                float* dHC  = scr;        // 32
                float* dCHt = scr + 32;   // 32
                float* dS   = scr + 64;   // 16
                float* dCof = scr + 80;   // 16
                float* dK   = scr + 96;   // 32
                {
                    float hc = 0.f, cht = 0.f;
                    #pragma unroll
                    for (int k = 0; k < 8; k++) {
                        hc  += Hs[i0*8 + k] * Pt[k*8 + j];
                        cht += Pt[qi*8 + k] * Hs[qj*8 + k];
                    }
                    dHC[l] = hc;  dCHt[l] = cht;
                }
                __syncwarp();
                if (l < 16) {
                    float sv = Rs[l];
                    #pragma unroll
                    for (int k = 0; k < 8; k++) sv += dHC[(l >> 2)*8 + k] * Hs[(l & 3)*8 + k];
                    dS[l] = sv;
                }
                __syncwarp();
                if (l < 16) dCof[l] = cof4t<float>(dS, l);
                __syncwarp();
                {
                    const float det  = dS[0]*dCof[0] + dS[1]*dCof[1] + dS[2]*dCof[2] + dS[3]*dCof[3];
                    const float rdet = 1.f / det;
                    float sv = 0.f;
                    #pragma unroll
                    for (int k = 0; k < 4; k++) sv += dCHt[qi*4 + k] * dCof[k*4 + qj];
                    dK[l] = sv * rdet;
                }
                __syncwarp();
                {
                    float su0 = 0.f, su1 = 0.f;
                    #pragma unroll
                    for (int k = 0; k < 4; k++) {
                        const float hckj = dHC[k*8 + j];
                        su0 += dK[i0*4 + k]     * hckj;
                        su1 += dK[(i0+4)*4 + k] * hckj;
                    }
                    sU[l]      = Pt[l]      - su0;
                    sU[32 + l] = Pt[32 + l] - su1;
                }
            }
        }
        __syncthreads();

        // ---------- R6-proven broadcast write loop ----------
        const float4 val = reinterpret_cast<const float4*>(sU)[tid & 15];
        float4* dst = reinterpret_cast<float4*>(out + MEANS_ELEMS)
                    + (size_t)t * 65536 + tid;
        #pragma unroll 8
        for (int it = 0; it < 256; it++) {
            __stcs(dst, val);
            dst += THREADS;
        }
    }
}

// ---------------------------------------------------------------------------
extern "C" void kernel_launch(void* const* d_in, const int* in_sizes, int n_in,
                              void* d_out, int out_size)
{
    const float* obs       = (const float*)d_in[0];
    const float* F         = (const float*)d_in[1];
    const float* H         = (const float*)d_in[2];
    const float* Q         = (const float*)d_in[3];
    const float* R         = (const float*)d_in[4];
    const float* init_mean = (const float*)d_in[5];
    const float* init_cov  = (const float*)d_in[6];
    float* out = (float*)d_out;

    fused_kernel<<<NB_TOTAL, THREADS>>>(obs, F, H, Q, R, init_mean, init_cov, out);
}

// round 11
// speedup vs baseline: 1.3600x; 1.3600x over previous
#include <cuda_runtime.h>
#include <cstdint>
#include <math.h>

#define T_STEPS 1000
#define BATCH   4096
#define T_EXACT 192
#define CHUNK   8
#define NCHUNK_EXACT 24                    // 192 / 8
#define NCHUNKS (T_STEPS / CHUNK)          // 125

#define SUPW    16
#define NCHAIN  12                         // 12 chains x 16 = 192

#define MEANS_ELEMS ((size_t)T_STEPS * BATCH * 8)
#define NB_MEAN  32
#define NB_TOTAL (NB_MEAN + T_STEPS)       // 1032
#define THREADS  256
#define FULLMASK 0xffffffffu

// rows 0..T_EXACT-1 = exact; row T_EXACT = steady state.
// per row: A_t = M_t@F (A_0 = M_0) [64] + K_t [32]
__device__ __align__(16) float g_MK[(T_EXACT + 1) * 96];
__device__ __align__(16) float g_U [(T_EXACT + 1) * 64];

// cofactor (r,c) of a 4x4, element index l = r*4+c
template <typename T>
__device__ __forceinline__ float cof4t(const T* S, int l) {
    int r = l >> 2, c = l & 3;
    int ra[3], ca[3];
    int n = 0;
    #pragma unroll
    for (int x = 0; x < 4; x++) if (x != r) ra[n++] = x;
    n = 0;
    #pragma unroll
    for (int x = 0; x < 4; x++) if (x != c) ca[n++] = x;
    double m00 = S[ra[0]*4+ca[0]], m01 = S[ra[0]*4+ca[1]], m02 = S[ra[0]*4+ca[2]];
    double m10 = S[ra[1]*4+ca[0]], m11 = S[ra[1]*4+ca[1]], m12 = S[ra[1]*4+ca[2]];
    double m20 = S[ra[2]*4+ca[0]], m21 = S[ra[2]*4+ca[1]], m22 = S[ra[2]*4+ca[2]];
    double d = m00*(m11*m22 - m12*m21) - m01*(m10*m22 - m12*m20) + m02*(m10*m21 - m11*m20);
    return (float)(((r + c) & 1) ? -d : d);
}

// warp-collective fp32 8x8 inverse, Gauss-Jordan + partial pivoting (proven R6-R10)
__device__ void inv8x8_f(const float* A, float* Ainv, int l) {
    float rA[8], rI[8];
    #pragma unroll
    for (int j = 0; j < 8; j++) {
        rA[j] = (l < 8) ? A[l*8 + j] : 0.f;
        rI[j] = (l == j) ? 1.f : 0.f;
    }
    #pragma unroll 1
    for (int k = 0; k < 8; k++) {
        float cand = (l >= k && l < 8) ? fabsf(rA[k]) : -1.f;
        int idx = (l < 8) ? l : 0;
        #pragma unroll
        for (int d = 1; d < 8; d <<= 1) {
            float oc = __shfl_xor_sync(FULLMASK, cand, d);
            int   oi = __shfl_xor_sync(FULLMASK, idx,  d);
            if (oc > cand || (oc == cand && oi < idx)) { cand = oc; idx = oi; }
        }
        const int piv = __shfl_sync(FULLMASK, idx, 0);
        const int src = (l == k) ? piv : ((l == piv) ? k : l);
        #pragma unroll
        for (int j = 0; j < 8; j++) {
            rA[j] = __shfl_sync(FULLMASK, rA[j], src);
            rI[j] = __shfl_sync(FULLMASK, rI[j], src);
        }
        float pA[8], pI[8];
        #pragma unroll
        for (int j = 0; j < 8; j++) {
            pA[j] = __shfl_sync(FULLMASK, rA[j], k);
            pI[j] = __shfl_sync(FULLMASK, rI[j], k);
        }
        const float inv = 1.f / pA[k];
        if (l == k) {
            #pragma unroll
            for (int j = 0; j < 8; j++) { rA[j] = pA[j]*inv; rI[j] = pI[j]*inv; }
        } else {
            const float f = rA[k] * inv;
            #pragma unroll
            for (int j = 0; j < 8; j++) { rA[j] -= f*pA[j]; rI[j] -= f*pI[j]; }
        }
    }
    if (l < 8) {
        #pragma unroll
        for (int j = 0; j < 8; j++) Ainv[l*8 + j] = rI[j];
    }
}

// One SDA doubling of the triple (W,V,U) in place (proven). scr: 256.
__device__ void sda_double(float* sW, float* sV, float* sU, float* scr, int l)
{
    float* phA = scr; float* phT = scr + 64; float* phB = scr + 128; float* phD = scr + 192;
    const int i0 = l >> 3, j = l & 7;
    {
        float s0 = 0.f, s1 = 0.f;
        #pragma unroll
        for (int k = 0; k < 8; k++) {
            const float ukj = sU[k*8 + j];
            s0 += sW[i0*8 + k]     * ukj;
            s1 += sW[(i0+4)*8 + k] * ukj;
        }
        phA[i0*8 + j]     = s0 + (i0 == j     ? 1.f : 0.f);
        phA[(i0+4)*8 + j] = s1 + (i0 + 4 == j ? 1.f : 0.f);
    }
    __syncwarp();
    inv8x8_f(phA, phT, l);
    __syncwarp();
    {
        float b0 = 0.f, b1 = 0.f, d0 = 0.f, d1 = 0.f;
        #pragma unroll
        for (int k = 0; k < 8; k++) {
            const float tkj = phT[k*8 + j];
            b0 += sV[i0*8 + k]     * tkj;
            b1 += sV[(i0+4)*8 + k] * tkj;
            d0 += sU[i0*8 + k]     * tkj;
            d1 += sU[(i0+4)*8 + k] * tkj;
        }
        phB[i0*8 + j] = b0;  phB[(i0+4)*8 + j] = b1;
        phD[i0*8 + j] = d0;  phD[(i0+4)*8 + j] = d1;
    }
    __syncwarp();
    {
        float c0 = 0.f, c1 = 0.f, e0 = 0.f, e1 = 0.f;
        #pragma unroll
        for (int k = 0; k < 8; k++) {
            const float wkj = sW[k*8 + j], vkj = sV[k*8 + j];
            c0 += phB[i0*8 + k]     * wkj;
            c1 += phB[(i0+4)*8 + k] * wkj;
            e0 += phD[i0*8 + k]     * vkj;
            e1 += phD[(i0+4)*8 + k] * vkj;
        }
        __syncwarp();
        phA[i0*8 + j] = c0;  phA[(i0+4)*8 + j] = c1;
        phT[i0*8 + j] = e0;  phT[(i0+4)*8 + j] = e1;
    }
    __syncwarp();
    {
        float wn0 = sW[i0*8 + j], wn1 = sW[(i0+4)*8 + j];
        float un0 = sU[i0*8 + j], un1 = sU[(i0+4)*8 + j];
        float vn0 = 0.f, vn1 = 0.f;
        #pragma unroll
        for (int k = 0; k < 8; k++) {
            wn0 += phA[i0*8 + k]     * sV[j*8 + k];
            wn1 += phA[(i0+4)*8 + k] * sV[j*8 + k];
            un0 += sV[k*8 + i0]      * phT[k*8 + j];
            un1 += sV[k*8 + i0 + 4]  * phT[k*8 + j];
            vn0 += phB[i0*8 + k]     * sV[k*8 + j];
            vn1 += phB[(i0+4)*8 + k] * sV[k*8 + j];
        }
        __syncwarp();
        sW[i0*8 + j] = wn0;  sW[(i0+4)*8 + j] = wn1;
        sU[i0*8 + j] = un0;  sU[(i0+4)*8 + j] = un1;
        sV[i0*8 + j] = vn0;  sV[(i0+4)*8 + j] = vn1;
    }
    __syncwarp();
}

// Composition Phi_c = Phi_a ∘ Phi_b (proven R8/R9 production). scr: 256.
__device__ void compose_triple(
    const float* Wa, const float* Va, const float* Ua,
    const float* Wb, const float* Vb, const float* Ub,
    float* Wc, float* Vc, float* Uc, float* scr, int l)
{
    const int i0 = l >> 3, j = l & 7;
    float* M1 = scr;
    float* T  = scr + 64;
    float* X  = scr + 128;
    float* N  = scr + 192;
    {
        float s0 = 0.f, s1 = 0.f;
        #pragma unroll
        for (int k = 0; k < 8; k++) {
            const float u = Ua[k*8 + j];
            s0 += Wb[i0*8 + k]     * u;
            s1 += Wb[(i0+4)*8 + k] * u;
        }
        M1[i0*8 + j]     = s0 + (i0 == j     ? 1.f : 0.f);
        M1[(i0+4)*8 + j] = s1 + (i0 + 4 == j ? 1.f : 0.f);
    }
    __syncwarp();
    inv8x8_f(M1, T, l);
    __syncwarp();
    {
        float x0 = 0.f, x1 = 0.f, n0 = 0.f, n1 = 0.f;
        #pragma unroll
        for (int k = 0; k < 8; k++) {
            const float t = T[k*8 + j];
            x0 += Va[i0*8 + k]     * t;
            x1 += Va[(i0+4)*8 + k] * t;
            n0 += Ua[i0*8 + k]     * t;
            n1 += Ua[(i0+4)*8 + k] * t;
        }
        X[i0*8 + j] = x0;  X[(i0+4)*8 + j] = x1;
        N[i0*8 + j] = n0;  N[(i0+4)*8 + j] = n1;
    }
    __syncwarp();
    {
        float v0 = 0.f, v1 = 0.f, w0 = 0.f, w1 = 0.f, q0 = 0.f, q1 = 0.f;
        #pragma unroll
        for (int k = 0; k < 8; k++) {
            const float vb = Vb[k*8 + j], wb = Wb[k*8 + j];
            v0 += X[i0*8 + k]     * vb;
            v1 += X[(i0+4)*8 + k] * vb;
            w0 += X[i0*8 + k]     * wb;
            w1 += X[(i0+4)*8 + k] * wb;
            q0 += N[i0*8 + k]     * vb;
            q1 += N[(i0+4)*8 + k] * vb;
        }
        __syncwarp();
        Vc[i0*8 + j] = v0;  Vc[(i0+4)*8 + j] = v1;
        M1[i0*8 + j] = w0;  M1[(i0+4)*8 + j] = w1;
        T [i0*8 + j] = q0;  T [(i0+4)*8 + j] = q1;
    }
    __syncwarp();
    {
        float wc0 = Wa[i0*8 + j], wc1 = Wa[(i0+4)*8 + j];
        float uc0 = Ub[i0*8 + j], uc1 = Ub[(i0+4)*8 + j];
        #pragma unroll
        for (int k = 0; k < 8; k++) {
            const float vajk = Va[j*8 + k], tkj = T[k*8 + j];
            wc0 += M1[i0*8 + k]     * vajk;
            wc1 += M1[(i0+4)*8 + k] * vajk;
            uc0 += Vb[k*8 + i0]     * tkj;
            uc1 += Vb[k*8 + i0 + 4] * tkj;
        }
        Wc[i0*8 + j] = wc0;  Wc[(i0+4)*8 + j] = wc1;
        Uc[i0*8 + j] = uc0;  Uc[(i0+4)*8 + j] = uc1;
    }
    __syncwarp();
}

// LFT apply: Pout = W + V P (I + U P)^-1 V^T (proven). scr: 256.
__device__ void apply_triple(const float* W, const float* V, const float* U,
                             const float* P, float* Pout, float* scr, int l)
{
    const int i0 = l >> 3, j = l & 7;
    float* M = scr;
    float* T = scr + 64;
    float* B = scr + 128;
    float* D = scr + 192;
    {
        float s0 = 0.f, s1 = 0.f;
        #pragma unroll
        for (int k = 0; k < 8; k++) {
            const float pkj = P[k*8 + j];
            s0 += U[i0*8 + k]     * pkj;
            s1 += U[(i0+4)*8 + k] * pkj;
        }
        M[i0*8 + j]     = s0 + (i0 == j     ? 1.f : 0.f);
        M[(i0+4)*8 + j] = s1 + (i0 + 4 == j ? 1.f : 0.f);
    }
    __syncwarp();
    inv8x8_f(M, T, l);
    __syncwarp();
    {
        float b0 = 0.f, b1 = 0.f;
        #pragma unroll
        for (int k = 0; k < 8; k++) {
            const float tkj = T[k*8 + j];
            b0 += P[i0*8 + k]     * tkj;
            b1 += P[(i0+4)*8 + k] * tkj;
        }
        B[i0*8 + j] = b0;  B[(i0+4)*8 + j] = b1;
    }
    __syncwarp();
    {
        float d0 = 0.f, d1 = 0.f;
        #pragma unroll
        for (int k = 0; k < 8; k++) {
            const float bkj = B[k*8 + j];
            d0 += V[i0*8 + k]     * bkj;
            d1 += V[(i0+4)*8 + k] * bkj;
        }
        D[i0*8 + j] = d0;  D[(i0+4)*8 + j] = d1;
    }
    __syncwarp();
    {
        float p0 = W[i0*8 + j], p1 = W[(i0+4)*8 + j];
        #pragma unroll
        for (int k = 0; k < 8; k++) {
            p0 += D[i0*8 + k]     * V[j*8 + k];
            p1 += D[(i0+4)*8 + k] * V[j*8 + k];
        }
        Pout[i0*8 + j] = p0;  Pout[(i0+4)*8 + j] = p1;
    }
    __syncwarp();
}

// ---------------------------------------------------------------------------
// Setup kernel — grid padded to 148 blocks to dodge the single-CTA issue
// throttle (pSmIssueThrottleCtrl; vanishes @grid>=148). Only block 0 works.
//   warp0: 7 doublings (snap Phi^16/32/64/128), then doublings 8,9 -> Phi^512
//   warps 1..9: composition tree -> Phi^{16k}, k=1..11
//   phase A: warps 1..11 restart covs; warp12: Pinf
//   phase C: warps 0..11: 12 parallel 16-step exact chains; warp12: steady row
// ---------------------------------------------------------------------------
__global__ void __launch_bounds__(512) setup_kernel(
    const float* __restrict__ F,
    const float* __restrict__ H,
    const float* __restrict__ Q,
    const float* __restrict__ R,
    const float* __restrict__ init_cov)
{
    if (blockIdx.x != 0) return;   // padding blocks (throttle workaround)

    __shared__ float Fs[64], Hs[32], Qs[64], Rs[16];
    __shared__ float sW[64], sV[64], sU[64];
    __shared__ float snap[4][192];          // Phi^16,32,64,128 (W|V|U)
    __shared__ float trip[12][192];         // Phi^{16k}, k=1..11
    __shared__ float sP[NCHAIN][64];        // restart covariances
    __shared__ float cw[16][288];           // per-warp scratch
    __shared__ float scr0[256];

    const int tid = threadIdx.x;
    const int wid = tid >> 5;
    const int l   = tid & 31;

    // ---------------- warp 0: init + 7 doublings ----------------
    if (wid == 0) {
        const int i0 = l >> 3, j = l & 7;
        Fs[l] = F[l];  Fs[32 + l] = F[32 + l];
        Qs[l] = Q[l];  Qs[32 + l] = Q[32 + l];
        Hs[l] = H[l];
        if (l < 16) Rs[l] = R[l];
        sP[0][l] = init_cov[l];  sP[0][32 + l] = init_cov[32 + l];
        __syncwarp();

        if (l < 16) scr0[l] = cof4t<float>(Rs, l);
        __syncwarp();
        {
            const float det  = Rs[0]*scr0[0] + Rs[1]*scr0[1] + Rs[2]*scr0[2] + Rs[3]*scr0[3];
            const float rdet = 1.f / det;
            float e0 = 0.f, e1 = 0.f;
            #pragma unroll
            for (int a = 0; a < 4; a++) {
                float t0 = 0.f;
                #pragma unroll
                for (int b = 0; b < 4; b++) t0 += scr0[b*4 + a] * Hs[b*8 + j];
                t0 *= rdet;
                e0 += Hs[a*8 + i0]     * t0;
                e1 += Hs[a*8 + i0 + 4] * t0;
            }
            sU[i0*8 + j] = e0;  sU[(i0+4)*8 + j] = e1;
            sW[l] = Qs[l];  sW[32 + l] = Qs[32 + l];
            sV[l] = Fs[l];  sV[32 + l] = Fs[32 + l];
        }
        __syncwarp();

        #pragma unroll 1
        for (int it = 0; it < 7; it++) {
            sda_double(sW, sV, sU, scr0, l);
            if (it >= 3) {
                float* s = snap[it - 3];
                s[l] = sW[l];        s[32 + l] = sW[32 + l];
                s[64 + l] = sV[l];   s[96 + l] = sV[32 + l];
                s[128 + l] = sU[l];  s[160 + l] = sU[32 + l];
                __syncwarp();
            }
        }
    }
    __syncthreads();

    // ---------------- level 1 compositions ----------------
    {
        if (wid >= 1 && wid <= 5) {
            // k: 3=16+32, 5=64+16, 6=64+32, 9=128+16, 10=128+32
            const int kk[6] = {0, 3, 5, 6, 9, 10};
            const int aa[6] = {0, 1, 2, 2, 3, 3};
            const int bb[6] = {0, 0, 0, 1, 0, 1};
            const float* A = snap[aa[wid]];
            const float* B = snap[bb[wid]];
            float* C = trip[kk[wid]];
            compose_triple(A, A + 64, A + 128, B, B + 64, B + 128,
                           C, C + 64, C + 128, cw[wid], l);
        } else if (wid >= 6 && wid <= 9) {
            const int k2[4] = {1, 2, 4, 8};
            const float* S = snap[wid - 6];
            float* C = trip[k2[wid - 6]];
            #pragma unroll
            for (int e = 0; e < 6; e++) C[e*32 + l] = S[e*32 + l];
        } else if (wid == 0) {
            sda_double(sW, sV, sU, scr0, l);          // doubling 8
        }
    }
    __syncthreads();

    // ---------------- level 2 compositions ----------------
    {
        if (wid == 1) {        // 7 = 64 ∘ 48(trip3)
            const float* A = snap[2];
            const float* B = trip[3];
            float* C = trip[7];
            compose_triple(A, A + 64, A + 128, B, B + 64, B + 128,
                           C, C + 64, C + 128, cw[wid], l);
        } else if (wid == 2) { // 11 = 128 ∘ 48(trip3)
            const float* A = snap[3];
            const float* B = trip[3];
            float* C = trip[11];
            compose_triple(A, A + 64, A + 128, B, B + 64, B + 128,
                           C, C + 64, C + 128, cw[wid], l);
        } else if (wid == 0) {
            sda_double(sW, sV, sU, scr0, l);          // doubling 9 -> Phi^512
        }
    }
    __syncthreads();

    // ---------------- phase A: restart covariances + Pinf ----------------
    {
        if (wid >= 1 && wid <= 11) {
            const float* Tk = trip[wid];
            apply_triple(Tk, Tk + 64, Tk + 128, sP[0], sP[wid], cw[wid], l);
        } else if (wid == 12) {
            apply_triple(sW, sV, sU, sP[0], cw[15], cw[12], l);   // Pinf -> cw[15][0..64)
        }
    }
    __syncthreads();

    // ---------------- phase C ----------------
    if (wid < NCHAIN) {
        const int t0 = wid * SUPW;
        float* c   = cw[wid];
        float* FPw = c;          float* HCw = c + 64;
        float* CHw = c + 96;     float* Sw  = c + 128;
        float* Cfw = c + 144;    float* Kw  = c + 160;
        float* Ww  = c + 192;    float* Mw  = c + 224;
        float* Pw  = sP[wid];

        const int i0 = l >> 3, j = l & 7;
        const int qi = l >> 2, qj = l & 3;

        #pragma unroll 1
        for (int s = 0; s < SUPW; s++) {
            const int t = t0 + s;
            {
                float fp0 = 0.f, fp1 = 0.f, hc = 0.f, cht = 0.f;
                #pragma unroll
                for (int k = 0; k < 8; k++) {
                    const float pkj = Pw[k*8 + j];
                    fp0 += Fs[i0*8 + k]     * pkj;
                    fp1 += Fs[(i0+4)*8 + k] * pkj;
                    hc  += Hs[i0*8 + k]     * pkj;
                    cht += Pw[qi*8 + k] * Hs[qj*8 + k];
                }
                FPw[l] = fp0;  FPw[32 + l] = fp1;
                HCw[l] = hc;   CHw[l] = cht;
            }
            __syncwarp();
            if (l < 16) {
                float sv = Rs[l];
                #pragma unroll
                for (int k = 0; k < 8; k++) sv += HCw[(l >> 2)*8 + k] * Hs[(l & 3)*8 + k];
                Sw[l] = sv;
            }
            __syncwarp();
            if (l < 16) Cfw[l] = cof4t<float>(Sw, l);
            __syncwarp();
            {
                const float det  = Sw[0]*Cfw[0] + Sw[1]*Cfw[1] + Sw[2]*Cfw[2] + Sw[3]*Cfw[3];
                const float rdet = 1.0f / det;
                float sv = 0.f;
                #pragma unroll
                for (int k = 0; k < 4; k++) sv += CHw[qi*4 + k] * Cfw[k*4 + qj];
                Kw[l] = sv * rdet;
            }
            __syncwarp();
            float u0, u1;
            {
                float su0 = 0.f, sm0 = 0.f, su1 = 0.f, sm1 = 0.f, wv = 0.f;
                #pragma unroll
                for (int k = 0; k < 4; k++) {
                    const float hckj = HCw[k*8 + j], hskj = Hs[k*8 + j];
                    su0 += Kw[i0*4 + k]     * hckj;
                    sm0 += Kw[i0*4 + k]     * hskj;
                    su1 += Kw[(i0+4)*4 + k] * hckj;
                    sm1 += Kw[(i0+4)*4 + k] * hskj;
                }
                #pragma unroll
                for (int k = 0; k < 8; k++) wv += Fs[qi*8 + k] * Kw[k*4 + qj];
                u0 = Pw[l] - su0;
                u1 = Pw[32 + l] - su1;
                Mw[l]      = (i0 == j     ? 1.0f : 0.0f) - sm0;
                Mw[32 + l] = (i0 + 4 == j ? 1.0f : 0.0f) - sm1;
                Ww[l] = wv;
            }
            __syncwarp();
            {
                float a0, a1;
                if (t == 0) { a0 = Mw[l];  a1 = Mw[32 + l]; }
                else {
                    a0 = 0.f;  a1 = 0.f;
                    #pragma unroll
                    for (int k = 0; k < 8; k++) {
                        const float fkj = Fs[k*8 + j];
                        a0 += Mw[i0*8 + k]     * fkj;
                        a1 += Mw[(i0+4)*8 + k] * fkj;
                    }
                }
                g_MK[t*96 + l]      = a0;
                g_MK[t*96 + 32 + l] = a1;
                g_MK[t*96 + 64 + l] = Kw[l];
                g_U [t*64 + l]      = u0;
                g_U [t*64 + 32 + l] = u1;

                const float w00 = Ww[i0*4+0],     w01 = Ww[i0*4+1],     w02 = Ww[i0*4+2],     w03 = Ww[i0*4+3];
                const float w10 = Ww[(i0+4)*4+0], w11 = Ww[(i0+4)*4+1], w12 = Ww[(i0+4)*4+2], w13 = Ww[(i0+4)*4+3];
                float p0 = Qs[l], p1 = Qs[32 + l];
                #pragma unroll
                for (int k = 0; k < 8; k++) {
                    const float h0 = HCw[k], h1 = HCw[8+k], h2 = HCw[16+k], h3 = HCw[24+k];
                    const float fjk = Fs[j*8 + k];
                    const float fu0 = FPw[i0*8 + k]     - (w00*h0 + w01*h1 + w02*h2 + w03*h3);
                    const float fu1 = FPw[(i0+4)*8 + k] - (w10*h0 + w11*h1 + w12*h2 + w13*h3);
                    p0 += fu0 * fjk;
                    p1 += fu1 * fjk;
                }
                Pw[l] = p0;  Pw[32 + l] = p1;
            }
            __syncwarp();
        }
    } else if (wid == 12) {
        // steady coefficient row from Pinf (cw[15][0..64)) — proven math
        const int i0 = l >> 3, j = l & 7;
        const int qi = l >> 2, qj = l & 3;
        const float* Pinf = cw[15];
        float* stHC  = cw[15] + 64;
        float* stCHt = cw[15] + 96;
        float* stS   = cw[15] + 128;
        float* stCof = cw[15] + 144;
        float* stK   = cw[15] + 160;
        float* stM   = cw[15] + 192;
        {
            float s = 0.f, c2 = 0.f;
            #pragma unroll
            for (int k = 0; k < 8; k++) {
                s  += Hs[i0*8 + k] * Pinf[k*8 + j];
                c2 += Pinf[qi*8 + k] * Hs[qj*8 + k];
            }
            stHC[l] = s;  stCHt[l] = c2;
        }
        __syncwarp();
        if (l < 16) {
            float s = Rs[l];
            #pragma unroll
            for (int k = 0; k < 8; k++) s += stHC[(l >> 2)*8 + k] * Hs[(l & 3)*8 + k];
            stS[l] = s;
        }
        __syncwarp();
        if (l < 16) stCof[l] = cof4t<float>(stS, l);
        __syncwarp();
        {
            const float det  = stS[0]*stCof[0] + stS[1]*stCof[1] + stS[2]*stCof[2] + stS[3]*stCof[3];
            const float rdet = 1.f / det;
            float s = 0.f;
            #pragma unroll
            for (int k = 0; k < 4; k++) s += stCHt[qi*4 + k] * stCof[k*4 + qj];
            stK[l] = s * rdet;
        }
        __syncwarp();
        {
            float m0 = 0.f, m1 = 0.f;
            #pragma unroll
            for (int k = 0; k < 4; k++) {
                const float hkj = Hs[k*8 + j];
                m0 += stK[i0*4 + k]     * hkj;
                m1 += stK[(i0+4)*4 + k] * hkj;
            }
            stM[i0*8 + j]     = (i0 == j     ? 1.f : 0.f) - m0;
            stM[(i0+4)*8 + j] = (i0 + 4 == j ? 1.f : 0.f) - m1;
        }
        __syncwarp();
        {
            float a0 = 0.f, a1 = 0.f, s0 = 0.f, s1 = 0.f;
            #pragma unroll
            for (int k = 0; k < 8; k++) {
                const float fkj = Fs[k*8 + j];
                a0 += stM[i0*8 + k]     * fkj;
                a1 += stM[(i0+4)*8 + k] * fkj;
            }
            #pragma unroll
            for (int k = 0; k < 4; k++) {
                const float hckj = stHC[k*8 + j];
                s0 += stK[i0*4 + k]     * hckj;
                s1 += stK[(i0+4)*4 + k] * hckj;
            }
            g_MK[T_EXACT*96 + l]      = a0;
            g_MK[T_EXACT*96 + 32 + l] = a1;
            g_MK[T_EXACT*96 + 64 + l] = stK[l];
            g_U [T_EXACT*64 + l]      = Pinf[i0*8 + j]     - s0;
            g_U [T_EXACT*64 + 32 + l] = Pinf[(i0+4)*8 + j] - s1;
        }
    }
}

// ---------------------------------------------------------------------------
// Main kernel — the proven-best combination (R6 bcast + R8 mean, (256,4)).
// ---------------------------------------------------------------------------
__global__ void __launch_bounds__(THREADS, 4) main_kernel(
    const float* __restrict__ obs,
    const float* __restrict__ init_mean,
    float* __restrict__ out)
{
    const int tid = threadIdx.x;

    if (blockIdx.x < NB_MEAN) {
        // ------------------ mean recursion (2 threads/batch) ------------------
        __shared__ float coef[CHUNK * 96];
        const int gtid = blockIdx.x * THREADS + tid;
        const int b    = gtid >> 1;
        const int half = gtid & 1;

        float st[8];
        #pragma unroll
        for (int i = 0; i < 8; i++) st[i] = init_mean[b*8 + i];

        for (int c = 0; c < NCHUNKS; c++) {
            if (c < NCHUNK_EXACT) {
                __syncthreads();
                if (tid < CHUNK*24)
                    reinterpret_cast<float4*>(coef)[tid] =
                        reinterpret_cast<const float4*>(&g_MK[c*(CHUNK*96)])[tid];
                __syncthreads();
            } else if (c == NCHUNK_EXACT) {
                __syncthreads();
                if (tid < 24)
                    reinterpret_cast<float4*>(coef)[tid] =
                        reinterpret_cast<const float4*>(&g_MK[T_EXACT*96])[tid];
                __syncthreads();
            }
            #pragma unroll
            for (int u = 0; u < CHUNK; u++) {
                const int t = c*CHUNK + u;
                const float* Cs = &coef[(c < NCHUNK_EXACT ? u : 0) * 96];

                const float4 zv = *reinterpret_cast<const float4*>(
                    &obs[((size_t)t*BATCH + b) * 4]);

                float y[4];
                #pragma unroll
                for (int r = 0; r < 4; r++) {
                    const int row = half*4 + r;
                    const float4 a0 = *reinterpret_cast<const float4*>(&Cs[row*8]);
                    const float4 a1 = *reinterpret_cast<const float4*>(&Cs[row*8 + 4]);
                    const float4 kk = *reinterpret_cast<const float4*>(&Cs[64 + row*4]);
                    y[r] = a0.x*st[0] + a0.y*st[1] + a0.z*st[2] + a0.w*st[3]
                         + a1.x*st[4] + a1.y*st[5] + a1.z*st[6] + a1.w*st[7]
                         + kk.x*zv.x + kk.y*zv.y + kk.z*zv.z + kk.w*zv.w;
                }

                __stcs(reinterpret_cast<float4*>(&out[((size_t)t*BATCH + b)*8 + half*4]),
                       make_float4(y[0], y[1], y[2], y[3]));

                const float o0 = __shfl_xor_sync(FULLMASK, y[0], 1);
                const float o1 = __shfl_xor_sync(FULLMASK, y[1], 1);
                const float o2 = __shfl_xor_sync(FULLMASK, y[2], 1);
                const float o3 = __shfl_xor_sync(FULLMASK, y[3], 1);
                st[0] = half ? o0   : y[0];
                st[1] = half ? o1   : y[1];
                st[2] = half ? o2   : y[2];
                st[3] = half ? o3   : y[3];
                st[4] = half ? y[0] : o0;
                st[5] = half ? y[1] : o1;
                st[6] = half ? y[2] : o2;
                st[7] = half ? y[3] : o3;
            }
        }
    } else {
        // ------------------ covariance broadcast: one tile per block ------------------
        const int t  = (int)blockIdx.x - NB_MEAN;            // 0..999
        const int tc = (t < T_EXACT) ? t : T_EXACT;
        const float4 val = reinterpret_cast<const float4*>(g_U)[tc*16 + (tid & 15)];

        float4* dst = reinterpret_cast<float4*>(out + MEANS_ELEMS)
                    + (size_t)t * 65536 + tid;
        #pragma unroll 8
        for (int it = 0; it < 256; it++) {
            __stcs(dst, val);
            dst += THREADS;
        }
    }
}

// ---------------------------------------------------------------------------
extern "C" void kernel_launch(void* const* d_in, const int* in_sizes, int n_in,
                              void* d_out, int out_size)
{
    const float* obs       = (const float*)d_in[0];
    const float* F         = (const float*)d_in[1];
    const float* H         = (const float*)d_in[2];
    const float* Q         = (const float*)d_in[3];
    const float* R         = (const float*)d_in[4];
    const float* init_mean = (const float*)d_in[5];
    const float* init_cov  = (const float*)d_in[6];
    float* out = (float*)d_out;

    setup_kernel<<<148, 512>>>(F, H, Q, R, init_cov);
    main_kernel<<<NB_TOTAL, THREADS>>>(obs, init_mean, out);
}

// round 12
// speedup vs baseline: 1.6348x; 1.2021x over previous
#include <cuda_runtime.h>
#include <cstdint>
#include <math.h>

#define T_STEPS 1000
#define BATCH   4096
#define T_EXACT 192
#define CHUNK   8
#define NCHUNK_EXACT 24                    // 192 / 8
#define NCHUNKS (T_STEPS / CHUNK)          // 125

#define SUPW    24
#define NCHAIN  8                          // 8 chains x 24 = 192

#define MEANS_ELEMS ((size_t)T_STEPS * BATCH * 8)
#define NB_MEAN  32
#define NFROZEN  (T_STEPS - T_EXACT)       // 808
#define NB_TOTAL (1 + NB_MEAN + T_STEPS)   // 1033
#define THREADS  256
#define FULLMASK 0xffffffffu

// rows 0..T_EXACT-1 = exact; row T_EXACT = steady state.
// per row: A_t = M_t@F (A_0 = M_0) [64] + K_t [32]
__device__ __align__(16) float g_MK[(T_EXACT + 1) * 96];
__device__ __align__(16) float g_U [(T_EXACT + 1) * 64];
__device__ int g_sflag;    // steady row published
__device__ int g_done;     // all exact rows published

__device__ __forceinline__ int ld_acq(const int* p) {
    int v; asm volatile("ld.global.acquire.gpu.b32 %0, [%1];" : "=r"(v) : "l"(p)); return v;
}
__device__ __forceinline__ void st_rel(int* p, int v) {
    asm volatile("st.global.release.gpu.b32 [%0], %1;" :: "l"(p), "r"(v) : "memory");
}

// cofactor (r,c) of a 4x4, element index l = r*4+c
template <typename T>
__device__ __forceinline__ float cof4t(const T* S, int l) {
    int r = l >> 2, c = l & 3;
    int ra[3], ca[3];
    int n = 0;
    #pragma unroll
    for (int x = 0; x < 4; x++) if (x != r) ra[n++] = x;
    n = 0;
    #pragma unroll
    for (int x = 0; x < 4; x++) if (x != c) ca[n++] = x;
    double m00 = S[ra[0]*4+ca[0]], m01 = S[ra[0]*4+ca[1]], m02 = S[ra[0]*4+ca[2]];
    double m10 = S[ra[1]*4+ca[0]], m11 = S[ra[1]*4+ca[1]], m12 = S[ra[1]*4+ca[2]];
    double m20 = S[ra[2]*4+ca[0]], m21 = S[ra[2]*4+ca[1]], m22 = S[ra[2]*4+ca[2]];
    double d = m00*(m11*m22 - m12*m21) - m01*(m10*m22 - m12*m20) + m02*(m10*m21 - m11*m20);
    return (float)(((r + c) & 1) ? -d : d);
}

// warp-collective fp32 8x8 inverse, Gauss-Jordan + partial pivoting (proven)
__device__ void inv8x8_f(const float* A, float* Ainv, int l) {
    float rA[8], rI[8];
    #pragma unroll
    for (int j = 0; j < 8; j++) {
        rA[j] = (l < 8) ? A[l*8 + j] : 0.f;
        rI[j] = (l == j) ? 1.f : 0.f;
    }
    #pragma unroll 1
    for (int k = 0; k < 8; k++) {
        float cand = (l >= k && l < 8) ? fabsf(rA[k]) : -1.f;
        int idx = (l < 8) ? l : 0;
        #pragma unroll
        for (int d = 1; d < 8; d <<= 1) {
            float oc = __shfl_xor_sync(FULLMASK, cand, d);
            int   oi = __shfl_xor_sync(FULLMASK, idx,  d);
            if (oc > cand || (oc == cand && oi < idx)) { cand = oc; idx = oi; }
        }
        const int piv = __shfl_sync(FULLMASK, idx, 0);
        const int src = (l == k) ? piv : ((l == piv) ? k : l);
        #pragma unroll
        for (int j = 0; j < 8; j++) {
            rA[j] = __shfl_sync(FULLMASK, rA[j], src);
            rI[j] = __shfl_sync(FULLMASK, rI[j], src);
        }
        float pA[8], pI[8];
        #pragma unroll
        for (int j = 0; j < 8; j++) {
            pA[j] = __shfl_sync(FULLMASK, rA[j], k);
            pI[j] = __shfl_sync(FULLMASK, rI[j], k);
        }
        const float inv = 1.f / pA[k];
        if (l == k) {
            #pragma unroll
            for (int j = 0; j < 8; j++) { rA[j] = pA[j]*inv; rI[j] = pI[j]*inv; }
        } else {
            const float f = rA[k] * inv;
            #pragma unroll
            for (int j = 0; j < 8; j++) { rA[j] -= f*pA[j]; rI[j] -= f*pI[j]; }
        }
    }
    if (l < 8) {
        #pragma unroll
        for (int j = 0; j < 8; j++) Ainv[l*8 + j] = rI[j];
    }
}

// One SDA doubling of the triple (W,V,U) in place (proven). scr: 256.
__device__ void sda_double(float* sW, float* sV, float* sU, float* scr, int l)
{
    float* phA = scr; float* phT = scr + 64; float* phB = scr + 128; float* phD = scr + 192;
    const int i0 = l >> 3, j = l & 7;
    {
        float s0 = 0.f, s1 = 0.f;
        #pragma unroll
        for (int k = 0; k < 8; k++) {
            const float ukj = sU[k*8 + j];
            s0 += sW[i0*8 + k]     * ukj;
            s1 += sW[(i0+4)*8 + k] * ukj;
        }
        phA[i0*8 + j]     = s0 + (i0 == j     ? 1.f : 0.f);
        phA[(i0+4)*8 + j] = s1 + (i0 + 4 == j ? 1.f : 0.f);
    }
    __syncwarp();
    inv8x8_f(phA, phT, l);
    __syncwarp();
    {
        float b0 = 0.f, b1 = 0.f, d0 = 0.f, d1 = 0.f;
        #pragma unroll
        for (int k = 0; k < 8; k++) {
            const float tkj = phT[k*8 + j];
            b0 += sV[i0*8 + k]     * tkj;
            b1 += sV[(i0+4)*8 + k] * tkj;
            d0 += sU[i0*8 + k]     * tkj;
            d1 += sU[(i0+4)*8 + k] * tkj;
        }
        phB[i0*8 + j] = b0;  phB[(i0+4)*8 + j] = b1;
        phD[i0*8 + j] = d0;  phD[(i0+4)*8 + j] = d1;
    }
    __syncwarp();
    {
        float c0 = 0.f, c1 = 0.f, e0 = 0.f, e1 = 0.f;
        #pragma unroll
        for (int k = 0; k < 8; k++) {
            const float wkj = sW[k*8 + j], vkj = sV[k*8 + j];
            c0 += phB[i0*8 + k]     * wkj;
            c1 += phB[(i0+4)*8 + k] * wkj;
            e0 += phD[i0*8 + k]     * vkj;
            e1 += phD[(i0+4)*8 + k] * vkj;
        }
        __syncwarp();
        phA[i0*8 + j] = c0;  phA[(i0+4)*8 + j] = c1;
        phT[i0*8 + j] = e0;  phT[(i0+4)*8 + j] = e1;
    }
    __syncwarp();
    {
        float wn0 = sW[i0*8 + j], wn1 = sW[(i0+4)*8 + j];
        float un0 = sU[i0*8 + j], un1 = sU[(i0+4)*8 + j];
        float vn0 = 0.f, vn1 = 0.f;
        #pragma unroll
        for (int k = 0; k < 8; k++) {
            wn0 += phA[i0*8 + k]     * sV[j*8 + k];
            wn1 += phA[(i0+4)*8 + k] * sV[j*8 + k];
            un0 += sV[k*8 + i0]      * phT[k*8 + j];
            un1 += sV[k*8 + i0 + 4]  * phT[k*8 + j];
            vn0 += phB[i0*8 + k]     * sV[k*8 + j];
            vn1 += phB[(i0+4)*8 + k] * sV[k*8 + j];
        }
        __syncwarp();
        sW[i0*8 + j] = wn0;  sW[(i0+4)*8 + j] = wn1;
        sU[i0*8 + j] = un0;  sU[(i0+4)*8 + j] = un1;
        sV[i0*8 + j] = vn0;  sV[(i0+4)*8 + j] = vn1;
    }
    __syncwarp();
}

// Composition Phi_c = Phi_a ∘ Phi_b (powers commute; proven). scr: 256.
__device__ void compose_triple(
    const float* Wa, const float* Va, const float* Ua,
    const float* Wb, const float* Vb, const float* Ub,
    float* Wc, float* Vc, float* Uc, float* scr, int l)
{
    const int i0 = l >> 3, j = l & 7;
    float* M1 = scr;
    float* T  = scr + 64;
    float* X  = scr + 128;
    float* N  = scr + 192;
    {
        float s0 = 0.f, s1 = 0.f;
        #pragma unroll
        for (int k = 0; k < 8; k++) {
            const float u = Ua[k*8 + j];
            s0 += Wb[i0*8 + k]     * u;
            s1 += Wb[(i0+4)*8 + k] * u;
        }
        M1[i0*8 + j]     = s0 + (i0 == j     ? 1.f : 0.f);
        M1[(i0+4)*8 + j] = s1 + (i0 + 4 == j ? 1.f : 0.f);
    }
    __syncwarp();
    inv8x8_f(M1, T, l);
    __syncwarp();
    {
        float x0 = 0.f, x1 = 0.f, n0 = 0.f, n1 = 0.f;
        #pragma unroll
        for (int k = 0; k < 8; k++) {
            const float t = T[k*8 + j];
            x0 += Va[i0*8 + k]     * t;
            x1 += Va[(i0+4)*8 + k] * t;
            n0 += Ua[i0*8 + k]     * t;
            n1 += Ua[(i0+4)*8 + k] * t;
        }
        X[i0*8 + j] = x0;  X[(i0+4)*8 + j] = x1;
        N[i0*8 + j] = n0;  N[(i0+4)*8 + j] = n1;
    }
    __syncwarp();
    {
        float v0 = 0.f, v1 = 0.f, w0 = 0.f, w1 = 0.f, q0 = 0.f, q1 = 0.f;
        #pragma unroll
        for (int k = 0; k < 8; k++) {
            const float vb = Vb[k*8 + j], wb = Wb[k*8 + j];
            v0 += X[i0*8 + k]     * vb;
            v1 += X[(i0+4)*8 + k] * vb;
            w0 += X[i0*8 + k]     * wb;
            w1 += X[(i0+4)*8 + k] * wb;
            q0 += N[i0*8 + k]     * vb;
            q1 += N[(i0+4)*8 + k] * vb;
        }
        __syncwarp();
        Vc[i0*8 + j] = v0;  Vc[(i0+4)*8 + j] = v1;
        M1[i0*8 + j] = w0;  M1[(i0+4)*8 + j] = w1;
        T [i0*8 + j] = q0;  T [(i0+4)*8 + j] = q1;
    }
    __syncwarp();
    {
        float wc0 = Wa[i0*8 + j], wc1 = Wa[(i0+4)*8 + j];
        float uc0 = Ub[i0*8 + j], uc1 = Ub[(i0+4)*8 + j];
        #pragma unroll
        for (int k = 0; k < 8; k++) {
            const float vajk = Va[j*8 + k], tkj = T[k*8 + j];
            wc0 += M1[i0*8 + k]     * vajk;
            wc1 += M1[(i0+4)*8 + k] * vajk;
            uc0 += Vb[k*8 + i0]     * tkj;
            uc1 += Vb[k*8 + i0 + 4] * tkj;
        }
        Wc[i0*8 + j] = wc0;  Wc[(i0+4)*8 + j] = wc1;
        Uc[i0*8 + j] = uc0;  Uc[(i0+4)*8 + j] = uc1;
    }
    __syncwarp();
}

// LFT apply: Pout = W + V P (I + U P)^-1 V^T (proven). scr: 256.
__device__ void apply_triple(const float* W, const float* V, const float* U,
                             const float* P, float* Pout, float* scr, int l)
{
    const int i0 = l >> 3, j = l & 7;
    float* M = scr;
    float* T = scr + 64;
    float* B = scr + 128;
    float* D = scr + 192;
    {
        float s0 = 0.f, s1 = 0.f;
        #pragma unroll
        for (int k = 0; k < 8; k++) {
            const float pkj = P[k*8 + j];
            s0 += U[i0*8 + k]     * pkj;
            s1 += U[(i0+4)*8 + k] * pkj;
        }
        M[i0*8 + j]     = s0 + (i0 == j     ? 1.f : 0.f);
        M[(i0+4)*8 + j] = s1 + (i0 + 4 == j ? 1.f : 0.f);
    }
    __syncwarp();
    inv8x8_f(M, T, l);
    __syncwarp();
    {
        float b0 = 0.f, b1 = 0.f;
        #pragma unroll
        for (int k = 0; k < 8; k++) {
            const float tkj = T[k*8 + j];
            b0 += P[i0*8 + k]     * tkj;
            b1 += P[(i0+4)*8 + k] * tkj;
        }
        B[i0*8 + j] = b0;  B[(i0+4)*8 + j] = b1;
    }
    __syncwarp();
    {
        float d0 = 0.f, d1 = 0.f;
        #pragma unroll
        for (int k = 0; k < 8; k++) {
            const float bkj = B[k*8 + j];
            d0 += V[i0*8 + k]     * bkj;
            d1 += V[(i0+4)*8 + k] * bkj;
        }
        D[i0*8 + j] = d0;  D[(i0+4)*8 + j] = d1;
    }
    __syncwarp();
    {
        float p0 = W[i0*8 + j], p1 = W[(i0+4)*8 + j];
        #pragma unroll
        for (int k = 0; k < 8; k++) {
            p0 += D[i0*8 + k]     * V[j*8 + k];
            p1 += D[(i0+4)*8 + k] * V[j*8 + k];
        }
        Pout[i0*8 + j] = p0;  Pout[(i0+4)*8 + j] = p1;
    }
    __syncwarp();
}

// ---------------------------------------------------------------------------
// SINGLE fused kernel.
//   block 0           : 8-warp setup pipeline (publishes g_sflag early, g_done)
//   blocks 1..32      : mean recursion (wait g_done ~20us)
//   blocks 33..840    : frozen cov tiles t=192..999 (wait g_sflag ~10us)
//   blocks 841..1032  : exact cov tiles t=0..191 (wait g_done)
// ---------------------------------------------------------------------------
__global__ void __launch_bounds__(THREADS, 4) fused_kernel(
    const float* __restrict__ obs,
    const float* __restrict__ F,
    const float* __restrict__ H,
    const float* __restrict__ Q,
    const float* __restrict__ R,
    const float* __restrict__ init_mean,
    const float* __restrict__ init_cov,
    float* __restrict__ out)
{
    // setup-block arrays
    __shared__ float Fs[64], Hs[32], Qs[64], Rs[16];
    __shared__ float sW[64], sV[64], sU[64];
    __shared__ float snap[5][192];          // Phi^8,16,32,64,128 (W|V|U)
    __shared__ float trip[8][192];          // Phi^{24k}, k=1..7
    __shared__ float sP[NCHAIN][64];        // restart covariances
    __shared__ float cw[NCHAIN][288];       // per-warp scratch
    __shared__ float scr0[256];
    // mean-block array
    __shared__ float coef[CHUNK * 96];

    const int tid = threadIdx.x;
    const int wid = tid >> 5;
    const int l   = tid & 31;

    if (blockIdx.x == 0) {
        // ==================== setup block (8 warps) ====================
        // ---- phase P0 (warp 0): init, E, 7 doublings (snap Phi^8..128)
        if (wid == 0) {
            const int i0 = l >> 3, j = l & 7;
            Fs[l] = F[l];  Fs[32 + l] = F[32 + l];
            Qs[l] = Q[l];  Qs[32 + l] = Q[32 + l];
            Hs[l] = H[l];
            if (l < 16) Rs[l] = R[l];
            sP[0][l] = init_cov[l];  sP[0][32 + l] = init_cov[32 + l];
            __syncwarp();

            if (l < 16) scr0[l] = cof4t<float>(Rs, l);
            __syncwarp();
            {
                const float det  = Rs[0]*scr0[0] + Rs[1]*scr0[1] + Rs[2]*scr0[2] + Rs[3]*scr0[3];
                const float rdet = 1.f / det;
                float e0 = 0.f, e1 = 0.f;
                #pragma unroll
                for (int a = 0; a < 4; a++) {
                    float t0 = 0.f;
                    #pragma unroll
                    for (int b = 0; b < 4; b++) t0 += scr0[b*4 + a] * Hs[b*8 + j];
                    t0 *= rdet;
                    e0 += Hs[a*8 + i0]     * t0;
                    e1 += Hs[a*8 + i0 + 4] * t0;
                }
                sU[i0*8 + j] = e0;  sU[(i0+4)*8 + j] = e1;
                sW[l] = Qs[l];  sW[32 + l] = Qs[32 + l];
                sV[l] = Fs[l];  sV[32 + l] = Fs[32 + l];
            }
            __syncwarp();

            #pragma unroll 1
            for (int it = 0; it < 7; it++) {
                sda_double(sW, sV, sU, scr0, l);
                if (it >= 2) {                       // Phi^8,16,32,64,128
                    float* s = snap[it - 2];
                    s[l] = sW[l];        s[32 + l] = sW[32 + l];
                    s[64 + l] = sV[l];   s[96 + l] = sV[32 + l];
                    s[128 + l] = sU[l];  s[160 + l] = sU[32 + l];
                    __syncwarp();
                }
            }
        }
        __syncthreads();

        // ---- L1: trip{1,2,3,4,6} = {24,48,72,96,144}; warp0: doubling 8
        {
            if (wid >= 1 && wid <= 5) {
                // k:      1=16∘8  2=32∘16  3=64∘8  4=64∘32  6=128∘16
                const int kk[6] = {0, 1, 2, 3, 4, 6};
                const int aa[6] = {0, 1, 2, 3, 3, 4};
                const int bb[6] = {0, 0, 1, 0, 2, 1};
                const float* A = snap[aa[wid]];
                const float* B = snap[bb[wid]];
                float* C = trip[kk[wid]];
                compose_triple(A, A + 64, A + 128, B, B + 64, B + 128,
                               C, C + 64, C + 128, cw[wid], l);
            } else if (wid == 0) {
                sda_double(sW, sV, sU, scr0, l);     // Phi^256
            }
        }
        __syncthreads();

        // ---- L2: trip5 = 120 = 72∘48; trip7 = 168 = 96∘72; warp0: doubling 9
        {
            if (wid == 1) {
                const float* A = trip[3];
                const float* B = trip[2];
                float* C = trip[5];
                compose_triple(A, A + 64, A + 128, B, B + 64, B + 128,
                               C, C + 64, C + 128, cw[wid], l);
            } else if (wid == 2) {
                const float* A = trip[4];
                const float* B = trip[3];
                float* C = trip[7];
                compose_triple(A, A + 64, A + 128, B, B + 64, B + 128,
                               C, C + 64, C + 128, cw[wid], l);
            } else if (wid == 0) {
                sda_double(sW, sV, sU, scr0, l);     // Phi^512
            }
        }
        __syncthreads();

        // ---- phase A: restart covs (warps 1-7); warp 0: Pinf + steady row + sflag
        if (wid >= 1 && wid <= 7) {
            const float* Tk = trip[wid];
            apply_triple(Tk, Tk + 64, Tk + 128, sP[0], sP[wid], cw[wid], l);
        } else if (wid == 0) {
            apply_triple(sW, sV, sU, sP[0], scr0, cw[0], l);   // Pinf -> scr0[0..64)
            // steady coefficient row from Pinf (proven math); scratch in cw[0]
            const int i0 = l >> 3, j = l & 7;
            const int qi = l >> 2, qj = l & 3;
            const float* Pinf = scr0;
            float* stHC  = cw[0];
            float* stCHt = cw[0] + 32;
            float* stS   = cw[0] + 64;
            float* stCof = cw[0] + 80;
            float* stK   = cw[0] + 96;
            float* stM   = cw[0] + 128;
            {
                float s = 0.f, c2 = 0.f;
                #pragma unroll
                for (int k = 0; k < 8; k++) {
                    s  += Hs[i0*8 + k] * Pinf[k*8 + j];
                    c2 += Pinf[qi*8 + k] * Hs[qj*8 + k];
                }
                stHC[l] = s;  stCHt[l] = c2;
            }
            __syncwarp();
            if (l < 16) {
                float s = Rs[l];
                #pragma unroll
                for (int k = 0; k < 8; k++) s += stHC[(l >> 2)*8 + k] * Hs[(l & 3)*8 + k];
                stS[l] = s;
            }
            __syncwarp();
            if (l < 16) stCof[l] = cof4t<float>(stS, l);
            __syncwarp();
            {
                const float det  = stS[0]*stCof[0] + stS[1]*stCof[1] + stS[2]*stCof[2] + stS[3]*stCof[3];
                const float rdet = 1.f / det;
                float s = 0.f;
                #pragma unroll
                for (int k = 0; k < 4; k++) s += stCHt[qi*4 + k] * stCof[k*4 + qj];
                stK[l] = s * rdet;
            }
            __syncwarp();
            {
                float m0 = 0.f, m1 = 0.f;
                #pragma unroll
                for (int k = 0; k < 4; k++) {
                    const float hkj = Hs[k*8 + j];
                    m0 += stK[i0*4 + k]     * hkj;
                    m1 += stK[(i0+4)*4 + k] * hkj;
                }
                stM[i0*8 + j]     = (i0 == j     ? 1.f : 0.f) - m0;
                stM[(i0+4)*8 + j] = (i0 + 4 == j ? 1.f : 0.f) - m1;
            }
            __syncwarp();
            {
                float a0 = 0.f, a1 = 0.f, s0 = 0.f, s1 = 0.f;
                #pragma unroll
                for (int k = 0; k < 8; k++) {
                    const float fkj = Fs[k*8 + j];
                    a0 += stM[i0*8 + k]     * fkj;
                    a1 += stM[(i0+4)*8 + k] * fkj;
                }
                #pragma unroll
                for (int k = 0; k < 4; k++) {
                    const float hckj = stHC[k*8 + j];
                    s0 += stK[i0*4 + k]     * hckj;
                    s1 += stK[(i0+4)*4 + k] * hckj;
                }
                g_MK[T_EXACT*96 + l]      = a0;
                g_MK[T_EXACT*96 + 32 + l] = a1;
                g_MK[T_EXACT*96 + 64 + l] = stK[l];
                g_U [T_EXACT*64 + l]      = Pinf[i0*8 + j]     - s0;
                g_U [T_EXACT*64 + 32 + l] = Pinf[(i0+4)*8 + j] - s1;
            }
            __syncwarp();
            __threadfence();
            __syncwarp();
            if (l == 0) st_rel(&g_sflag, 1);       // frozen region unblocked
        }
        __syncthreads();

        // ---- phase C: 8 parallel 24-step exact chains
        {
            const int t0 = wid * SUPW;
            float* c   = cw[wid];
            float* FPw = c;          float* HCw = c + 64;
            float* CHw = c + 96;     float* Sw  = c + 128;
            float* Cfw = c + 144;    float* Kw  = c + 160;
            float* Ww  = c + 192;    float* Mw  = c + 224;
            float* Pw  = sP[wid];

            const int i0 = l >> 3, j = l & 7;
            const int qi = l >> 2, qj = l & 3;

            #pragma unroll 1
            for (int s = 0; s < SUPW; s++) {
                const int t = t0 + s;
                {
                    float fp0 = 0.f, fp1 = 0.f, hc = 0.f, cht = 0.f;
                    #pragma unroll
                    for (int k = 0; k < 8; k++) {
                        const float pkj = Pw[k*8 + j];
                        fp0 += Fs[i0*8 + k]     * pkj;
                        fp1 += Fs[(i0+4)*8 + k] * pkj;
                        hc  += Hs[i0*8 + k]     * pkj;
                        cht += Pw[qi*8 + k] * Hs[qj*8 + k];
                    }
                    FPw[l] = fp0;  FPw[32 + l] = fp1;
                    HCw[l] = hc;   CHw[l] = cht;
                }
                __syncwarp();
                if (l < 16) {
                    float sv = Rs[l];
                    #pragma unroll
                    for (int k = 0; k < 8; k++) sv += HCw[(l >> 2)*8 + k] * Hs[(l & 3)*8 + k];
                    Sw[l] = sv;
                }
                __syncwarp();
                if (l < 16) Cfw[l] = cof4t<float>(Sw, l);
                __syncwarp();
                {
                    const float det  = Sw[0]*Cfw[0] + Sw[1]*Cfw[1] + Sw[2]*Cfw[2] + Sw[3]*Cfw[3];
                    const float rdet = 1.0f / det;
                    float sv = 0.f;
                    #pragma unroll
                    for (int k = 0; k < 4; k++) sv += CHw[qi*4 + k] * Cfw[k*4 + qj];
                    Kw[l] = sv * rdet;
                }
                __syncwarp();
                float u0, u1;
                {
                    float su0 = 0.f, sm0 = 0.f, su1 = 0.f, sm1 = 0.f, wv = 0.f;
                    #pragma unroll
                    for (int k = 0; k < 4; k++) {
                        const float hckj = HCw[k*8 + j], hskj = Hs[k*8 + j];
                        su0 += Kw[i0*4 + k]     * hckj;
                        sm0 += Kw[i0*4 + k]     * hskj;
                        su1 += Kw[(i0+4)*4 + k] * hckj;
                        sm1 += Kw[(i0+4)*4 + k] * hskj;
                    }
                    #pragma unroll
                    for (int k = 0; k < 8; k++) wv += Fs[qi*8 + k] * Kw[k*4 + qj];
                    u0 = Pw[l] - su0;
                    u1 = Pw[32 + l] - su1;
                    Mw[l]      = (i0 == j     ? 1.0f : 0.0f) - sm0;
                    Mw[32 + l] = (i0 + 4 == j ? 1.0f : 0.0f) - sm1;
                    Ww[l] = wv;
                }
                __syncwarp();
                {
                    float a0, a1;
                    if (t == 0) { a0 = Mw[l];  a1 = Mw[32 + l]; }
                    else {
                        a0 = 0.f;  a1 = 0.f;
                        #pragma unroll
                        for (int k = 0; k < 8; k++) {
                            const float fkj = Fs[k*8 + j];
                            a0 += Mw[i0*8 + k]     * fkj;
                            a1 += Mw[(i0+4)*8 + k] * fkj;
                        }
                    }
                    g_MK[t*96 + l]      = a0;
                    g_MK[t*96 + 32 + l] = a1;
                    g_MK[t*96 + 64 + l] = Kw[l];
                    g_U [t*64 + l]      = u0;
                    g_U [t*64 + 32 + l] = u1;

                    const float w00 = Ww[i0*4+0],     w01 = Ww[i0*4+1],     w02 = Ww[i0*4+2],     w03 = Ww[i0*4+3];
                    const float w10 = Ww[(i0+4)*4+0], w11 = Ww[(i0+4)*4+1], w12 = Ww[(i0+4)*4+2], w13 = Ww[(i0+4)*4+3];
                    float p0 = Qs[l], p1 = Qs[32 + l];
                    #pragma unroll
                    for (int k = 0; k < 8; k++) {
                        const float h0 = HCw[k], h1 = HCw[8+k], h2 = HCw[16+k], h3 = HCw[24+k];
                        const float fjk = Fs[j*8 + k];
                        const float fu0 = FPw[i0*8 + k]     - (w00*h0 + w01*h1 + w02*h2 + w03*h3);
                        const float fu1 = FPw[(i0+4)*8 + k] - (w10*h0 + w11*h1 + w12*h2 + w13*h3);
                        p0 += fu0 * fjk;
                        p1 += fu1 * fjk;
                    }
                    Pw[l] = p0;  Pw[32 + l] = p1;
                }
                __syncwarp();
            }
        }
        __threadfence();
        __syncthreads();
        if (tid == 0) st_rel(&g_done, 1);          // exact region unblocked
    } else if (blockIdx.x <= NB_MEAN) {
        // ==================== mean recursion (2 threads/batch) ====================
        const int gtid = ((int)blockIdx.x - 1) * THREADS + tid;
        const int b    = gtid >> 1;
        const int half = gtid & 1;

        float st[8];
        #pragma unroll
        for (int i = 0; i < 8; i++) st[i] = init_mean[b*8 + i];

        if (tid == 0)
            while (ld_acq(&g_done) == 0) __nanosleep(64);
        __syncthreads();

        for (int c = 0; c < NCHUNKS; c++) {
            if (c < NCHUNK_EXACT) {
                __syncthreads();
                if (tid < CHUNK*24)
                    reinterpret_cast<float4*>(coef)[tid] =
                        reinterpret_cast<const float4*>(&g_MK[c*(CHUNK*96)])[tid];
                __syncthreads();
            } else if (c == NCHUNK_EXACT) {
                __syncthreads();
                if (tid < 24)
                    reinterpret_cast<float4*>(coef)[tid] =
                        reinterpret_cast<const float4*>(&g_MK[T_EXACT*96])[tid];
                __syncthreads();
            }
            #pragma unroll
            for (int u = 0; u < CHUNK; u++) {
                const int t = c*CHUNK + u;
                const float* Cs = &coef[(c < NCHUNK_EXACT ? u : 0) * 96];

                const float4 zv = *reinterpret_cast<const float4*>(
                    &obs[((size_t)t*BATCH + b) * 4]);

                float y[4];
                #pragma unroll
                for (int r = 0; r < 4; r++) {
                    const int row = half*4 + r;
                    const float4 a0 = *reinterpret_cast<const float4*>(&Cs[row*8]);
                    const float4 a1 = *reinterpret_cast<const float4*>(&Cs[row*8 + 4]);
                    const float4 kk = *reinterpret_cast<const float4*>(&Cs[64 + row*4]);
                    y[r] = a0.x*st[0] + a0.y*st[1] + a0.z*st[2] + a0.w*st[3]
                         + a1.x*st[4] + a1.y*st[5] + a1.z*st[6] + a1.w*st[7]
                         + kk.x*zv.x + kk.y*zv.y + kk.z*zv.z + kk.w*zv.w;
                }

                __stcs(reinterpret_cast<float4*>(&out[((size_t)t*BATCH + b)*8 + half*4]),
                       make_float4(y[0], y[1], y[2], y[3]));

                const float o0 = __shfl_xor_sync(FULLMASK, y[0], 1);
                const float o1 = __shfl_xor_sync(FULLMASK, y[1], 1);
                const float o2 = __shfl_xor_sync(FULLMASK, y[2], 1);
                const float o3 = __shfl_xor_sync(FULLMASK, y[3], 1);
                st[0] = half ? o0   : y[0];
                st[1] = half ? o1   : y[1];
                st[2] = half ? o2   : y[2];
                st[3] = half ? o3   : y[3];
                st[4] = half ? y[0] : o0;
                st[5] = half ? y[1] : o1;
                st[6] = half ? y[2] : o2;
                st[7] = half ? y[3] : o3;
            }
        }
    } else {
        // ==================== covariance broadcast: one tile per block ====================
        int t, row;
        if (blockIdx.x <= NB_MEAN + NFROZEN) {
            t   = T_EXACT + ((int)blockIdx.x - NB_MEAN - 1);   // frozen: 192..999
            row = T_EXACT;
            if (tid == 0)
                while (ld_acq(&g_sflag) == 0) __nanosleep(64);
        } else {
            t   = (int)blockIdx.x - NB_MEAN - NFROZEN - 1;     // exact: 0..191
            row = t;
            if (tid == 0)
                while (ld_acq(&g_done) == 0) __nanosleep(64);
        }
        __syncthreads();

        const float4 val = reinterpret_cast<const float4*>(g_U)[row*16 + (tid & 15)];
        float4* dst = reinterpret_cast<float4*>(out + MEANS_ELEMS)
                    + (size_t)t * 65536 + tid;
        #pragma unroll 8
        for (int it = 0; it < 256; it++) {
            __stcs(dst, val);
            dst += THREADS;
        }
    }
}

// ---------------------------------------------------------------------------
extern "C" void kernel_launch(void* const* d_in, const int* in_sizes, int n_in,
                              void* d_out, int out_size)
{
    const float* obs       = (const float*)d_in[0];
    const float* F         = (const float*)d_in[1];
    const float* H         = (const float*)d_in[2];
    const float* Q         = (const float*)d_in[3];
    const float* R         = (const float*)d_in[4];
    const float* init_mean = (const float*)d_in[5];
    const float* init_cov  = (const float*)d_in[6];
    float* out = (float*)d_out;

    fused_kernel<<<NB_TOTAL, THREADS>>>(obs, F, H, Q, R, init_mean, init_cov, out);
}